// round 17
// baseline (speedup 1.0000x reference)
#include <cuda_runtime.h>
#include <cstdint>

#define Bq 4
#define Mq 8192
#define Nq 8192
#define Fq 288
#define NODESQ 16384
#define ROWSQ 32768

// Scratch (static device globals — no allocations allowed)
__device__ float g_h1[(size_t)ROWSQ * Fq];
__device__ float g_Wt1[Fq * Fq];   // W1^T tf32-rounded, k-QUAD layout (below)
__device__ float g_Wt2[Fq * Fq];
__device__ int   g_deg[Bq * NODESQ];   // zero at module load; dsc_kernel re-zeros
__device__ float g_dsc[Bq * NODESQ];
__device__ float g_style[Fq];      // relu(b1)

// ---------------------------------------------------------------------------
__device__ __forceinline__ uint32_t smem_u32(const void* p) {
    uint32_t a;
    asm("{ .reg .u64 t; cvta.to.shared.u64 t, %1; cvt.u32.u64 %0, t; }"
        : "=r"(a) : "l"(p));
    return a;
}
__device__ __forceinline__ uint32_t f2tf32(float x) {
    uint32_t r;
    asm("cvt.rna.tf32.f32 %0, %1;" : "=r"(r) : "f"(x));
    return r;
}
__device__ __forceinline__ void mma_tf32(float* c, const uint32_t* a,
                                         uint32_t b0, uint32_t b1) {
    asm volatile(
        "mma.sync.aligned.m16n8k8.row.col.f32.tf32.tf32.f32 "
        "{%0,%1,%2,%3}, {%4,%5,%6,%7}, {%8,%9}, {%0,%1,%2,%3};"
        : "+f"(c[0]), "+f"(c[1]), "+f"(c[2]), "+f"(c[3])
        : "r"(a[0]), "r"(a[1]), "r"(a[2]), "r"(a[3]), "r"(b0), "r"(b1));
}
#define CP_ASYNC16(dst, src) \
    asm volatile("cp.async.cg.shared.global [%0], [%1], 16;" \
                 :: "r"(dst), "l"(src) : "memory")
#define CP_COMMIT() asm volatile("cp.async.commit_group;" ::: "memory")
#define CP_WAIT1()  asm volatile("cp.async.wait_group 1;" ::: "memory")

// ---------------------------------------------------------------------------
// prep kernels (2 launches; fused layers are launches 3 and 4)
// ---------------------------------------------------------------------------
// k-QUAD position of k within its 32-chunk:
//   ks = r>>3, m = r&7, lc = m&3, half = m>>2
//   pos = lc*8 + ks*2 + half
// -> for each lc, the 8 floats (ks=0..3, halves) are CONTIGUOUS, so the
//    consumer loads all four (k,k+4) pairs with two LDS.128.
//    Bank check @PB=36: start bank (36*lr + 8*lc (+4)) mod 32 covers all 32
//    banks once per 8-lane phase for both loads — conflict-free.
__device__ __forceinline__ int kpair_pos(int k) {
    int c = k >> 5, r = k & 31, ks = r >> 3, m = r & 7;
    return c * 32 + (m & 3) * 8 + ks * 2 + (m >> 2);
}

// blocks 0..161: tf32 k-quad transpose of W1/W2; blocks 162+: histogram
__global__ void prep0_kernel(const float* __restrict__ W1,
                             const float* __restrict__ W2,
                             const int* __restrict__ idx_k1,
                             const int* __restrict__ idx_k2) {
    if (blockIdx.x >= 162) {
        int e = (blockIdx.x - 162) * 256 + threadIdx.x;
        if (e < Bq * Mq * 8) {
            int b = e >> 16;
            atomicAdd(&g_deg[b * NODESQ + idx_k2[e]], 1);
            atomicAdd(&g_deg[b * NODESQ + Mq + idx_k1[e]], 1);
        }
        return;
    }
    __shared__ float tile[32][33];
    int t = blockIdx.x;                // 0..161
    int z = t / 81; t -= z * 81;
    int ky = t / 9, nx = t - ky * 9;
    const float* W = z ? W2 : W1;
    float* Wt = z ? g_Wt2 : g_Wt1;
    int kb = ky * 32, nb = nx * 32;
    int tx = threadIdx.x & 31, ty = threadIdx.x >> 5;
#pragma unroll
    for (int dy = ty; dy < 32; dy += 8)
        tile[dy][tx] = W[(size_t)(kb + dy) * Fq + nb + tx];
    __syncthreads();
#pragma unroll
    for (int dy = ty; dy < 32; dy += 8)
        Wt[(size_t)(nb + dy) * Fq + kpair_pos(kb + tx)] =
            __uint_as_float(f2tf32(tile[tx][dy]));
}

// computes dsc and RE-ZEROS g_deg so the next kernel_launch (graph replay)
// starts from zero again (module load provides the first zero state).
__global__ void dsc_kernel(const float* __restrict__ b1) {
    int i = blockIdx.x * blockDim.x + threadIdx.x;
    if (i < Bq * NODESQ) {
        int d = g_deg[i];
        g_deg[i] = 0;
        g_dsc[i] = rsqrtf((float)(d > 1 ? d : 1));
    }
    if (i < Fq) g_style[i] = fmaxf(b1[i], 0.0f);
}

// ---------------------------------------------------------------------------
// Fused gather + tf32 GEMM (champion structure, frozen).
// 512 threads, CTA = 64 rows x N=288. KC=32, 9 chunks, one sync pair/chunk.
// Gather: row = tid>>3, q = tid&7 -> each LDG.128 covers 4 full aligned
//   128B lines. A double-buffered, pitch 36. Table reads via LDS.128 pairs.
// W: k-QUAD layout via 3-stage cp.async ring, pitch 36 -> per (j): two
//   conflict-free LDS.128 deliver all four ks B-pairs. A-frags preloaded.
// ---------------------------------------------------------------------------
#define FM 64
#define PA 36
#define PB 36
#define FNCH 9
#define NT 512
// smem float offsets
#define STY_FL 2048                     // after 64*16 uint2 table
#define A_FL   2112
#define AST    (FM * PA)                // 2304
#define B_FL   (A_FL + 2 * AST)         // 6720
#define BST    (Fq * PB)                // 10368
#define FSMEM  ((B_FL + 3 * BST) * 4)   // 151296 B

template <bool LAYER2, bool RELU>
__global__ void __launch_bounds__(NT, 1) fused_layer_kernel(
    const float* __restrict__ srcC,   // L1: feat_c | L2: g_h1
    const float* __restrict__ srcS,   // L1: feat_s | L2: unused
    const int* __restrict__ idx_k1,
    const int* __restrict__ idx_k2,
    const float* __restrict__ Wt,     // k-quad tf32 W^T
    const float* __restrict__ bias,
    float* __restrict__ C) {
    extern __shared__ float sm[];
    const uint32_t smBase = smem_u32(sm);
    const int tid = threadIdx.x;
    const int wid = tid >> 5, lane = tid & 31;
    const int wm = wid >> 2, wn = wid & 3;       // 4m x 4n warps (16x72 tiles)
    const int lr = lane >> 2, lc = lane & 3;
    const int row = tid >> 3;                    // 0..63
    const int q = tid & 7;                       // 16B slot in 128B unit
    const int rowBase = blockIdx.x * FM;
    const int b = rowBase >> 13;

    uint2* tabS = (uint2*)sm;
    uint4* tabS4 = (uint4*)sm;                   // paired view: 8 uint4 per row

    // ---- W cp.async streamer (chunk c covers k in [c*32, c*32+32)) ----
    auto issueB = [&](int c) {
        const uint32_t bB = smBase + (uint32_t)(B_FL + (c % 3) * BST) * 4;
        const float* g0 = Wt + c * 32;
#pragma unroll
        for (int t = 0; t < 5; t++) {
            int i = tid + t * NT;                // 0..2303
            if (i < Fq * 8) {
                int n = i >> 3, qq = i & 7;
                CP_ASYNC16(bB + (uint32_t)(n * PB + qq * 4) * 4,
                           g0 + (size_t)n * Fq + qq * 4);
            }
        }
        CP_COMMIT();
    };
    issueB(0);
    issueB(1);

    // ---- build gather table in smem (one thread per row) ----
    if (tid < FM) {
        int grow = rowBase + tid;
        const float* dscB = g_dsc + b * NODESQ;
        const int4* i2 = (const int4*)(idx_k2 + (size_t)grow * 8);
        const int4* i1 = (const int4*)(idx_k1 + (size_t)grow * 8);
        int4 a2 = __ldg(i2), c2 = __ldg(i2 + 1);
        int4 a1 = __ldg(i1), c1 = __ldg(i1 + 1);
        int id2[8] = {a2.x, a2.y, a2.z, a2.w, c2.x, c2.y, c2.z, c2.w};
        int id1[8] = {a1.x, a1.y, a1.z, a1.w, c1.x, c1.y, c1.z, c1.w};
#pragma unroll
        for (int j = 0; j < 8; j++) {
            uint32_t off = (uint32_t)(b * Mq + id2[j]) * (Fq * 4);
            float sc = dscB[id2[j]] * 0.25f;
            tabS[tid * 16 + j] = make_uint2(off, __float_as_uint(sc));
        }
        if (LAYER2) {
            float ss = 0.0f;
#pragma unroll
            for (int j = 0; j < 8; j++) ss += dscB[Mq + id1[j]];
            sm[STY_FL + tid] = ss * 0.25f;
        } else {
#pragma unroll
            for (int j = 0; j < 8; j++) {
                uint32_t off = (uint32_t)(b * Nq + id1[j]) * (Fq * 4);
                float sc = dscB[Mq + id1[j]] * 0.25f;
                tabS[tid * 16 + 8 + j] = make_uint2(off, __float_as_uint(sc));
            }
        }
    }
    __syncthreads();

    constexpr int NPAIR = LAYER2 ? 4 : 8;        // uint4 entry-pairs per row
    const char* baseC = (const char*)srcC;
    const char* baseS = (const char*)srcS;

    float4 ga;
    auto gatherChunk = [&](int c) {
        const uint32_t boff = (uint32_t)(c * 128 + q * 16);
        if (LAYER2) {
            float4 sv = __ldg((const float4*)g_style + c * 8 + q);
            float ss = sm[STY_FL + row];
            ga = make_float4(ss * sv.x, ss * sv.y, ss * sv.z, ss * sv.w);
        } else {
            ga = make_float4(0.f, 0.f, 0.f, 0.f);
        }
#pragma unroll
        for (int p = 0; p < NPAIR; p++) {
            const char* base = (!LAYER2 && p >= 4) ? baseS : baseC;
            uint4 e = tabS4[row * 8 + p];        // two table entries
            float4 v0 = __ldg((const float4*)(base + e.x + boff));
            float4 v1 = __ldg((const float4*)(base + e.z + boff));
            float s0 = __uint_as_float(e.y), s1 = __uint_as_float(e.w);
            ga.x = fmaf(v0.x, s0, ga.x); ga.y = fmaf(v0.y, s0, ga.y);
            ga.z = fmaf(v0.z, s0, ga.z); ga.w = fmaf(v0.w, s0, ga.w);
            ga.x = fmaf(v1.x, s1, ga.x); ga.y = fmaf(v1.y, s1, ga.y);
            ga.z = fmaf(v1.z, s1, ga.z); ga.w = fmaf(v1.w, s1, ga.w);
        }
    };
    auto stsChunk = [&](int c) {
        uint4 w;
        w.x = f2tf32(ga.x); w.y = f2tf32(ga.y);
        w.z = f2tf32(ga.z); w.w = f2tf32(ga.w);
        *(uint4*)(sm + A_FL + (c & 1) * AST + row * PA + q * 4) = w;
    };

    gatherChunk(0);
    stsChunk(0);

    float acc[9][4];
#pragma unroll
    for (int j = 0; j < 9; j++)
#pragma unroll
        for (int e = 0; e < 4; e++) acc[j][e] = 0.0f;

#pragma unroll
    for (int c = 0; c < FNCH; c++) {
        CP_WAIT1();
        __syncthreads();

        if (c + 2 < FNCH) issueB(c + 2);
        else CP_COMMIT();

        if (c + 1 < FNCH) gatherChunk(c + 1);   // LDGs overlap MMA below

        const float* aS = sm + A_FL + (c & 1) * AST;
        const float* bS = sm + B_FL + (c % 3) * BST;

        // preload all A fragments for this chunk (16 LDS.32)
        uint32_t a[4][4];
#pragma unroll
        for (int ks = 0; ks < 4; ks++) {
            const int k0 = ks * 8 + lc;
            const int r = wm * 16 + lr;
            a[ks][0] = __float_as_uint(aS[r * PA + k0]);
            a[ks][1] = __float_as_uint(aS[(r + 8) * PA + k0]);
            a[ks][2] = __float_as_uint(aS[r * PA + k0 + 4]);
            a[ks][3] = __float_as_uint(aS[(r + 8) * PA + k0 + 4]);
        }

        // j-outer: two LDS.128 per j deliver all 4 ks B-pairs
#pragma unroll
        for (int j = 0; j < 9; j++) {
            const int n = wn * 72 + j * 8 + lr;
            const float* bp = bS + n * PB + lc * 8;
            float4 b01 = *(const float4*)bp;         // ks=0,1 pairs
            float4 b23 = *(const float4*)(bp + 4);   // ks=2,3 pairs
            mma_tf32(acc[j], a[0], __float_as_uint(b01.x), __float_as_uint(b01.y));
            mma_tf32(acc[j], a[1], __float_as_uint(b01.z), __float_as_uint(b01.w));
            mma_tf32(acc[j], a[2], __float_as_uint(b23.x), __float_as_uint(b23.y));
            mma_tf32(acc[j], a[3], __float_as_uint(b23.z), __float_as_uint(b23.w));
        }

        if (c + 1 < FNCH) stsChunk(c + 1);
    }

    // ---- epilogue ----
    {
        size_t r = (size_t)rowBase + wm * 16 + lr;
        float* C0 = C + r * Fq;
        float* C1 = C + (r + 8) * Fq;
#pragma unroll
        for (int j = 0; j < 9; j++) {
            int col = wn * 72 + j * 8 + 2 * lc;
            float2 bb = *(const float2*)(bias + col);
            float2 v0, v1;
            v0.x = acc[j][0] + bb.x; v0.y = acc[j][1] + bb.y;
            v1.x = acc[j][2] + bb.x; v1.y = acc[j][3] + bb.y;
            if (RELU) {
                v0.x = fmaxf(v0.x, 0.f); v0.y = fmaxf(v0.y, 0.f);
                v1.x = fmaxf(v1.x, 0.f); v1.y = fmaxf(v1.y, 0.f);
            }
            *(float2*)(C0 + col) = v0;
            *(float2*)(C1 + col) = v1;
        }
    }
}

// ---------------------------------------------------------------------------
extern "C" void kernel_launch(void* const* d_in, const int* in_sizes, int n_in,
                              void* d_out, int out_size) {
    const float* feat_c = (const float*)d_in[0];
    const float* feat_s = (const float*)d_in[1];
    const int*   idx_k1 = (const int*)d_in[2];
    const int*   idx_k2 = (const int*)d_in[3];
    const float* W1     = (const float*)d_in[4];
    const float* b1     = (const float*)d_in[5];
    const float* W2     = (const float*)d_in[6];
    const float* b2     = (const float*)d_in[7];
    float* out = (float*)d_out;

    float* h1;  cudaGetSymbolAddress((void**)&h1,  g_h1);
    float* wt1; cudaGetSymbolAddress((void**)&wt1, g_Wt1);
    float* wt2; cudaGetSymbolAddress((void**)&wt2, g_Wt2);

    cudaFuncSetAttribute(fused_layer_kernel<false, true>,
                         cudaFuncAttributeMaxDynamicSharedMemorySize, FSMEM);
    cudaFuncSetAttribute(fused_layer_kernel<true, false>,
                         cudaFuncAttributeMaxDynamicSharedMemorySize, FSMEM);

    // prep (2 launches). g_deg: zero at module load; dsc_kernel re-zeros
    // after reading, so every graph replay sees deg=0 at histogram time.
    prep0_kernel<<<162 + (Bq * Mq * 8 + 255) / 256, 256>>>(W1, W2, idx_k1, idx_k2);
    dsc_kernel<<<(Bq * NODESQ + 255) / 256, 256>>>(b1);

    // layer 1: h1 = relu(gather(feat) @ W1 + b1)
    fused_layer_kernel<false, true><<<ROWSQ / FM, NT, FSMEM>>>(
        feat_c, feat_s, idx_k1, idx_k2, wt1, b1, h1);

    // layer 2: out = gather(h1, style) @ W2 + b2
    fused_layer_kernel<true, false><<<ROWSQ / FM, NT, FSMEM>>>(
        h1, nullptr, idx_k1, idx_k2, wt2, b2, out);
}